// round 2
// baseline (speedup 1.0000x reference)
#include <cuda_runtime.h>
#include <math.h>

#define BATCH 4
#define DCH   512
#define NSEQ  1536
#define NHEAD 8
#define HDIM  64

// ---------------- scratch (device globals; no runtime allocation) ----------
__device__ float g_q[BATCH * DCH * NSEQ];
__device__ float g_k[BATCH * DCH * NSEQ];
__device__ float g_v[BATCH * DCH * NSEQ];
__device__ float g_x[BATCH * DCH * NSEQ];
__device__ float g_scores[(size_t)BATCH * NHEAD * NSEQ * NSEQ]; // 302 MB
__device__ float g_min;

// ---------------- helpers ---------------------------------------------------
__device__ __forceinline__ void atomicMinFloat(float* addr, float val) {
    if (val >= 0.0f) atomicMin((int*)addr, __float_as_int(val));
    else             atomicMax((unsigned int*)addr, __float_as_uint(val));
}

__global__ void init_min_kernel() { g_min = 3.402823466e38f; }

// ---------------- 1x1 conv as GEMM: Y[b,o,n] = sum_c W[o,c] X[b,c,n] + bias[o]
// grid (NSEQ/64, DCH/64, BATCH), block (16,16)
__global__ void gemm_proj_kernel(const float* __restrict__ W,
                                 const float* __restrict__ X,
                                 const float* __restrict__ bias,
                                 float* __restrict__ Y) {
    __shared__ float As[16][65];   // [c][o]
    __shared__ float Bs[16][64];   // [c][n]
    const int b  = blockIdx.z;
    const int o0 = blockIdx.y * 64;
    const int n0 = blockIdx.x * 64;
    const float* Xb = X + (size_t)b * DCH * NSEQ;
    float*       Yb = Y + (size_t)b * DCH * NSEQ;
    const int tid = threadIdx.y * 16 + threadIdx.x;
    float acc[4][4] = {};

    for (int k0 = 0; k0 < DCH; k0 += 16) {
        #pragma unroll
        for (int i = tid; i < 1024; i += 256) {
            int c = i & 15, o = i >> 4;          // c fastest -> coalesced W row read
            As[c][o] = W[(o0 + o) * DCH + k0 + c];
        }
        #pragma unroll
        for (int i = tid; i < 1024; i += 256) {
            int c = i >> 6, n = i & 63;
            Bs[c][n] = Xb[(size_t)(k0 + c) * NSEQ + n0 + n];
        }
        __syncthreads();
        #pragma unroll
        for (int c = 0; c < 16; c++) {
            float ra[4], rb[4];
            #pragma unroll
            for (int i = 0; i < 4; i++) ra[i] = As[c][threadIdx.y * 4 + i];
            #pragma unroll
            for (int j = 0; j < 4; j++) rb[j] = Bs[c][threadIdx.x * 4 + j];
            #pragma unroll
            for (int i = 0; i < 4; i++)
                #pragma unroll
                for (int j = 0; j < 4; j++)
                    acc[i][j] += ra[i] * rb[j];
        }
        __syncthreads();
    }
    #pragma unroll
    for (int i = 0; i < 4; i++) {
        int o = o0 + threadIdx.y * 4 + i;
        float bv = bias[o];
        #pragma unroll
        for (int j = 0; j < 4; j++)
            Yb[(size_t)o * NSEQ + n0 + threadIdx.x * 4 + j] = acc[i][j] + bv;
    }
}

// ---------------- scores[b,h,n,m] = (q_h^T k_h)/8, plus global min reduction
// head h owns channels c = dim*8 + h. grid (N/64 m, N/64 n, B*H), block (16,16)
__global__ void attn_scores_kernel() {
    const int z = blockIdx.z, b = z >> 3, h = z & 7;
    const int n0 = blockIdx.y * 64, m0 = blockIdx.x * 64;
    const float* qb = g_q + (size_t)b * DCH * NSEQ + (size_t)h * NSEQ;
    const float* kb = g_k + (size_t)b * DCH * NSEQ + (size_t)h * NSEQ;
    __shared__ float Qs[64][65];   // [dim][n]
    __shared__ float Ks[64][65];   // [dim][m]
    const int tid = threadIdx.y * 16 + threadIdx.x;

    #pragma unroll
    for (int i = tid; i < 4096; i += 256) {
        int dim = i >> 6, c = i & 63;
        size_t off = (size_t)dim * 8 * NSEQ;
        Qs[dim][c] = qb[off + n0 + c];
        Ks[dim][c] = kb[off + m0 + c];
    }
    __syncthreads();

    float acc[4][4] = {};
    #pragma unroll
    for (int dim = 0; dim < 64; dim++) {
        float ra[4], rb[4];
        #pragma unroll
        for (int i = 0; i < 4; i++) ra[i] = Qs[dim][threadIdx.y * 4 + i];
        #pragma unroll
        for (int j = 0; j < 4; j++) rb[j] = Ks[dim][threadIdx.x * 4 + j];
        #pragma unroll
        for (int i = 0; i < 4; i++)
            #pragma unroll
            for (int j = 0; j < 4; j++)
                acc[i][j] += ra[i] * rb[j];
    }

    float lmin = 3.402823466e38f;
    #pragma unroll
    for (int i = 0; i < 4; i++) {
        size_t rowo = ((size_t)z * NSEQ + n0 + threadIdx.y * 4 + i) * NSEQ;
        #pragma unroll
        for (int j = 0; j < 4; j++) {
            float s = acc[i][j] * 0.125f;   // 1/sqrt(64)
            g_scores[rowo + m0 + threadIdx.x * 4 + j] = s;
            lmin = fminf(lmin, s);
        }
    }
    __shared__ float red[256];
    red[tid] = lmin; __syncthreads();
    #pragma unroll
    for (int st = 128; st > 0; st >>= 1) {
        if (tid < st) red[tid] = fminf(red[tid], red[tid + st]);
        __syncthreads();
    }
    if (tid == 0) atomicMinFloat(&g_min, red[0]);
}

// ---------------- penalty + softmax (in place) + head-mean -> d_out part 2
// one block per (b, n): processes all 8 heads, no atomics. grid (NSEQ, BATCH), 256 thr
__global__ void softmax_mean_kernel(const int* __restrict__ maskw,
                                    float* __restrict__ out_mean) {
    const int n = blockIdx.x, b = blockIdx.y, tid = threadIdx.x;
    __shared__ float red[256];
    float pen[6], macc[6];
    const float minv = g_min - 20.0f;
    #pragma unroll
    for (int k = 0; k < 6; k++) {
        int m = tid + k * 256;
        // nonzero-bits test: correct for int32 {0,1} and float32 {0.0f,1.0f}
        pen[k]  = (maskw[n * NSEQ + m] != 0) ? 0.0f : minv;
        macc[k] = 0.0f;
    }
    for (int h = 0; h < NHEAD; h++) {
        float* row = g_scores + ((size_t)((b * NHEAD + h) * NSEQ + n)) * NSEQ;
        float s[6];
        float lmax = -3.402823466e38f;
        #pragma unroll
        for (int k = 0; k < 6; k++) {
            float v = row[tid + k * 256] + pen[k];
            s[k] = v; macc[k] += v;
            lmax = fmaxf(lmax, v);
        }
        red[tid] = lmax; __syncthreads();
        #pragma unroll
        for (int st = 128; st > 0; st >>= 1) {
            if (tid < st) red[tid] = fmaxf(red[tid], red[tid + st]);
            __syncthreads();
        }
        const float rmax = red[0]; __syncthreads();
        float lsum = 0.0f;
        #pragma unroll
        for (int k = 0; k < 6; k++) { s[k] = __expf(s[k] - rmax); lsum += s[k]; }
        red[tid] = lsum; __syncthreads();
        #pragma unroll
        for (int st = 128; st > 0; st >>= 1) {
            if (tid < st) red[tid] += red[tid + st];
            __syncthreads();
        }
        const float inv = 1.0f / red[0]; __syncthreads();
        #pragma unroll
        for (int k = 0; k < 6; k++) row[tid + k * 256] = s[k] * inv;
    }
    float* om = out_mean + ((size_t)(b * NSEQ + n)) * NSEQ;
    #pragma unroll
    for (int k = 0; k < 6; k++) om[tid + k * 256] = macc[k] * 0.125f; // mean over 8 heads
}

// ---------------- x[b, dim*8+h, n] = sum_m prob[b,h,n,m] v[b, dim*8+h, m]
// grid (N/64, 1, B*H), block (16,16); tile [64 n][64 dim], K=1536 in chunks of 16
__global__ void attn_pv_kernel() {
    const int z = blockIdx.z, b = z >> 3, h = z & 7;
    const int n0 = blockIdx.x * 64;
    const float* prow = g_scores + ((size_t)z * NSEQ + n0) * NSEQ;
    const float* vb   = g_v + (size_t)b * DCH * NSEQ + (size_t)h * NSEQ;
    __shared__ float Ps[16][65];   // [m][n]
    __shared__ float Vs[16][65];   // [m][dim]
    const int tid = threadIdx.y * 16 + threadIdx.x;
    float acc[4][4] = {};

    for (int k0 = 0; k0 < NSEQ; k0 += 16) {
        #pragma unroll
        for (int i = tid; i < 1024; i += 256) {
            int r = i >> 4, m = i & 15;        // m fastest -> 16-wide coalesced
            Ps[m][r] = prow[(size_t)r * NSEQ + k0 + m];
            Vs[m][r] = vb[(size_t)r * 8 * NSEQ + k0 + m];
        }
        __syncthreads();
        #pragma unroll
        for (int m = 0; m < 16; m++) {
            float ra[4], rb[4];
            #pragma unroll
            for (int i = 0; i < 4; i++) ra[i] = Ps[m][threadIdx.y * 4 + i];
            #pragma unroll
            for (int j = 0; j < 4; j++) rb[j] = Vs[m][threadIdx.x * 4 + j];
            #pragma unroll
            for (int i = 0; i < 4; i++)
                #pragma unroll
                for (int j = 0; j < 4; j++)
                    acc[i][j] += ra[i] * rb[j];
        }
        __syncthreads();
    }
    float* xb = g_x + (size_t)b * DCH * NSEQ + (size_t)h * NSEQ;
    #pragma unroll
    for (int j = 0; j < 4; j++) {
        int dim = threadIdx.x * 4 + j;
        #pragma unroll
        for (int i = 0; i < 4; i++)
            xb[(size_t)dim * 8 * NSEQ + n0 + threadIdx.y * 4 + i] = acc[i][j];
    }
}

// ---------------- launch ----------------------------------------------------
extern "C" void kernel_launch(void* const* d_in, const int* in_sizes, int n_in,
                              void* d_out, int out_size) {
    const float* query = (const float*)d_in[0];
    const float* key   = (const float*)d_in[1];
    const float* value = (const float*)d_in[2];
    // d_in[3] = dist (unused by the reference)
    const int*   maskw = (const int*)d_in[4];
    const float* Wq = (const float*)d_in[5];
    const float* bq = (const float*)d_in[6];
    const float* Wk = (const float*)d_in[7];
    const float* bk = (const float*)d_in[8];
    const float* Wv = (const float*)d_in[9];
    const float* bv = (const float*)d_in[10];
    const float* Wm = (const float*)d_in[11];
    const float* bm = (const float*)d_in[12];

    float* out      = (float*)d_out;                      // [B, D, N]
    float* out_mean = out + (size_t)BATCH * DCH * NSEQ;   // [B, N, N]

    float *qp, *kp, *vp, *xp;
    cudaGetSymbolAddress((void**)&qp, g_q);
    cudaGetSymbolAddress((void**)&kp, g_k);
    cudaGetSymbolAddress((void**)&vp, g_v);
    cudaGetSymbolAddress((void**)&xp, g_x);

    dim3 blk(16, 16);
    dim3 grid_proj(NSEQ / 64, DCH / 64, BATCH);
    dim3 grid_sc(NSEQ / 64, NSEQ / 64, BATCH * NHEAD);
    dim3 grid_pv(NSEQ / 64, 1, BATCH * NHEAD);
    dim3 grid_sm(NSEQ, BATCH);

    init_min_kernel<<<1, 1>>>();
    gemm_proj_kernel<<<grid_proj, blk>>>(Wq, query, bq, qp);
    gemm_proj_kernel<<<grid_proj, blk>>>(Wk, key,   bk, kp);
    gemm_proj_kernel<<<grid_proj, blk>>>(Wv, value, bv, vp);
    attn_scores_kernel<<<grid_sc, blk>>>();
    softmax_mean_kernel<<<grid_sm, 256>>>(maskw, out_mean);
    attn_pv_kernel<<<grid_pv, blk>>>();
    gemm_proj_kernel<<<grid_proj, blk>>>(Wm, xp, bm, out);
}

// round 3
// speedup vs baseline: 2.6824x; 2.6824x over previous
#include <cuda_runtime.h>
#include <math.h>
#include <stdint.h>

#define BATCH 4
#define DCH   512
#define NSEQ  1536
#define NHEAD 8
#define HDIM  64

// ---------------- scratch (device globals; no runtime allocation) ----------
__device__ float g_q[BATCH * DCH * NSEQ];
__device__ float g_k[BATCH * DCH * NSEQ];
__device__ float g_v[BATCH * DCH * NSEQ];
__device__ float g_x[BATCH * DCH * NSEQ];
__device__ float g_scores[(size_t)BATCH * NHEAD * NSEQ * NSEQ]; // 302 MB
__device__ float g_min;

// ---------------- helpers ---------------------------------------------------
__device__ __forceinline__ void atomicMinFloat(float* addr, float val) {
    if (val >= 0.0f) atomicMin((int*)addr, __float_as_int(val));
    else             atomicMax((unsigned int*)addr, __float_as_uint(val));
}

__device__ __forceinline__ uint32_t f2tf32(float f) {
    uint32_t u;
    asm("cvt.rna.tf32.f32 %0, %1;" : "=r"(u) : "f"(f));
    return u;
}

// m16n8k8 tf32 MMA, fp32 accumulate.
// A frag (16x8): a0=(g,tg) a1=(g+8,tg) a2=(g,tg+4) a3=(g+8,tg+4); g=lane>>2, tg=lane&3
// B frag (8x8):  b0=(tg,g) b1=(tg+4,g)
// C frag (16x8): c0=(g,2tg) c1=(g,2tg+1) c2=(g+8,2tg) c3=(g+8,2tg+1)
__device__ __forceinline__ void mma_tf32(float* c, const uint32_t* a, const uint32_t* b) {
    asm volatile(
        "mma.sync.aligned.m16n8k8.row.col.f32.tf32.tf32.f32 "
        "{%0,%1,%2,%3}, {%4,%5,%6,%7}, {%8,%9}, {%0,%1,%2,%3};"
        : "+f"(c[0]), "+f"(c[1]), "+f"(c[2]), "+f"(c[3])
        : "r"(a[0]), "r"(a[1]), "r"(a[2]), "r"(a[3]), "r"(b[0]), "r"(b[1]));
}

__global__ void init_min_kernel() { g_min = 3.402823466e38f; }

// =======================================================================
// Projection GEMM (tensor core): Y[b,o,n] = sum_c W[o,c] X[b,c,n] + bias[o]
// block tile 128(o) x 128(n), BK=16, 8 warps (2x4), warp tile 64x32
// grid (NSEQ/128, DCH/128, BATCH), 256 threads
// =======================================================================
__global__ __launch_bounds__(256) void gemm_proj_tc(const float* __restrict__ W,
                                                    const float* __restrict__ X,
                                                    const float* __restrict__ bias,
                                                    float* __restrict__ Y) {
    __shared__ uint32_t As[16][136];   // As[k][o]   (8k+o banks -> conflict-free frags)
    __shared__ uint32_t Bs[16][136];   // Bs[k][n]
    const int b  = blockIdx.z;
    const int o0 = blockIdx.y * 128;
    const int n0 = blockIdx.x * 128;
    const float* Xb = X + (size_t)b * DCH * NSEQ;
    float*       Yb = Y + (size_t)b * DCH * NSEQ;
    const int tid = threadIdx.x;
    const int warp = tid >> 5, lane = tid & 31;
    const int g = lane >> 2, tg = lane & 3;
    const int mo = (warp >> 2) * 64;   // warp M origin within block
    const int no = (warp & 3) * 32;    // warp N origin within block

    float acc[4][4][4] = {};

    for (int k0 = 0; k0 < DCH; k0 += 16) {
        // A: 128 o x 16 k  (coalesced: 4 lanes cover one o-row of 16 c)
        #pragma unroll
        for (int r = 0; r < 2; r++) {
            int i = r * 256 + tid;
            int o = i >> 2, kq = i & 3;
            float4 w4 = *(const float4*)(W + (size_t)(o0 + o) * DCH + k0 + kq * 4);
            As[kq * 4 + 0][o] = f2tf32(w4.x);
            As[kq * 4 + 1][o] = f2tf32(w4.y);
            As[kq * 4 + 2][o] = f2tf32(w4.z);
            As[kq * 4 + 3][o] = f2tf32(w4.w);
        }
        // B: 16 k x 128 n (fully coalesced, vector smem store)
        #pragma unroll
        for (int r = 0; r < 2; r++) {
            int i = r * 256 + tid;
            int k = i >> 5, nq = i & 31;
            float4 x4 = *(const float4*)(Xb + (size_t)(k0 + k) * NSEQ + n0 + nq * 4);
            uint4 u = make_uint4(f2tf32(x4.x), f2tf32(x4.y), f2tf32(x4.z), f2tf32(x4.w));
            *(uint4*)&Bs[k][nq * 4] = u;
        }
        __syncthreads();
        #pragma unroll
        for (int kk = 0; kk < 16; kk += 8) {
            uint32_t a[4][4], bb[4][2];
            #pragma unroll
            for (int i = 0; i < 4; i++) {
                a[i][0] = As[kk + tg][mo + i * 16 + g];
                a[i][1] = As[kk + tg][mo + i * 16 + 8 + g];
                a[i][2] = As[kk + tg + 4][mo + i * 16 + g];
                a[i][3] = As[kk + tg + 4][mo + i * 16 + 8 + g];
            }
            #pragma unroll
            for (int j = 0; j < 4; j++) {
                bb[j][0] = Bs[kk + tg][no + j * 8 + g];
                bb[j][1] = Bs[kk + tg + 4][no + j * 8 + g];
            }
            #pragma unroll
            for (int i = 0; i < 4; i++)
                #pragma unroll
                for (int j = 0; j < 4; j++)
                    mma_tf32(acc[i][j], a[i], bb[j]);
        }
        __syncthreads();
    }
    // epilogue: bias + store (float2 per c-pair)
    #pragma unroll
    for (int i = 0; i < 4; i++) {
        int r0 = o0 + mo + i * 16 + g;
        int r1 = r0 + 8;
        float bv0 = bias[r0], bv1 = bias[r1];
        #pragma unroll
        for (int j = 0; j < 4; j++) {
            int col = n0 + no + j * 8 + 2 * tg;
            float2 v0 = make_float2(acc[i][j][0] + bv0, acc[i][j][1] + bv0);
            float2 v1 = make_float2(acc[i][j][2] + bv1, acc[i][j][3] + bv1);
            *(float2*)&Yb[(size_t)r0 * NSEQ + col] = v0;
            *(float2*)&Yb[(size_t)r1 * NSEQ + col] = v1;
        }
    }
}

// =======================================================================
// Scores (tensor core): S[b,h,n,m] = (1/8) sum_d q[d,n] k[d,m]; global min
// head h channels: c = d*8+h. block tile 128(n) x 128(m), K=64 in 4 chunks
// grid (NSEQ/128 m, NSEQ/128 n, B*H), 256 threads
// =======================================================================
__global__ __launch_bounds__(256) void attn_scores_tc() {
    __shared__ uint32_t As[16][136];   // As[d][n]
    __shared__ uint32_t Bs[16][136];   // Bs[d][m]
    const int z = blockIdx.z, b = z >> 3, h = z & 7;
    const int n0 = blockIdx.y * 128, m0 = blockIdx.x * 128;
    const float* qb = g_q + (size_t)b * DCH * NSEQ + (size_t)h * NSEQ;
    const float* kb = g_k + (size_t)b * DCH * NSEQ + (size_t)h * NSEQ;
    const int tid = threadIdx.x;
    const int warp = tid >> 5, lane = tid & 31;
    const int g = lane >> 2, tg = lane & 3;
    const int mo = (warp >> 2) * 64;
    const int no = (warp & 3) * 32;

    float acc[4][4][4] = {};

    for (int k0 = 0; k0 < HDIM; k0 += 16) {
        #pragma unroll
        for (int r = 0; r < 2; r++) {
            int i = r * 256 + tid;
            int d = i >> 5, nq = i & 31;
            size_t roff = (size_t)(k0 + d) * 8 * NSEQ;
            float4 q4 = *(const float4*)(qb + roff + n0 + nq * 4);
            float4 k4 = *(const float4*)(kb + roff + m0 + nq * 4);
            *(uint4*)&As[d][nq * 4] = make_uint4(f2tf32(q4.x), f2tf32(q4.y), f2tf32(q4.z), f2tf32(q4.w));
            *(uint4*)&Bs[d][nq * 4] = make_uint4(f2tf32(k4.x), f2tf32(k4.y), f2tf32(k4.z), f2tf32(k4.w));
        }
        __syncthreads();
        #pragma unroll
        for (int kk = 0; kk < 16; kk += 8) {
            uint32_t a[4][4], bb[4][2];
            #pragma unroll
            for (int i = 0; i < 4; i++) {
                a[i][0] = As[kk + tg][mo + i * 16 + g];
                a[i][1] = As[kk + tg][mo + i * 16 + 8 + g];
                a[i][2] = As[kk + tg + 4][mo + i * 16 + g];
                a[i][3] = As[kk + tg + 4][mo + i * 16 + 8 + g];
            }
            #pragma unroll
            for (int j = 0; j < 4; j++) {
                bb[j][0] = Bs[kk + tg][no + j * 8 + g];
                bb[j][1] = Bs[kk + tg + 4][no + j * 8 + g];
            }
            #pragma unroll
            for (int i = 0; i < 4; i++)
                #pragma unroll
                for (int j = 0; j < 4; j++)
                    mma_tf32(acc[i][j], a[i], bb[j]);
        }
        __syncthreads();
    }
    // epilogue: scale, store, min-reduce
    float lmin = 3.402823466e38f;
    const size_t sbase = (size_t)z * NSEQ * NSEQ;
    #pragma unroll
    for (int i = 0; i < 4; i++) {
        int r0 = n0 + mo + i * 16 + g;
        int r1 = r0 + 8;
        #pragma unroll
        for (int j = 0; j < 4; j++) {
            int col = m0 + no + j * 8 + 2 * tg;
            float s0 = acc[i][j][0] * 0.125f, s1 = acc[i][j][1] * 0.125f;
            float s2 = acc[i][j][2] * 0.125f, s3 = acc[i][j][3] * 0.125f;
            lmin = fminf(lmin, fminf(fminf(s0, s1), fminf(s2, s3)));
            *(float2*)&g_scores[sbase + (size_t)r0 * NSEQ + col] = make_float2(s0, s1);
            *(float2*)&g_scores[sbase + (size_t)r1 * NSEQ + col] = make_float2(s2, s3);
        }
    }
    #pragma unroll
    for (int o = 16; o > 0; o >>= 1)
        lmin = fminf(lmin, __shfl_xor_sync(0xFFFFFFFFu, lmin, o));
    __shared__ float red[8];
    if (lane == 0) red[warp] = lmin;
    __syncthreads();
    if (warp == 0) {
        float v = (lane < 8) ? red[lane] : 3.402823466e38f;
        #pragma unroll
        for (int o = 4; o > 0; o >>= 1)
            v = fminf(v, __shfl_xor_sync(0xFFFFFFFFu, v, o));
        if (lane == 0) atomicMinFloat(&g_min, v);
    }
}

// =======================================================================
// penalty + softmax (in place) + head-mean. one block per (b, n).
// =======================================================================
__global__ void softmax_mean_kernel(const int* __restrict__ maskw,
                                    float* __restrict__ out_mean) {
    const int n = blockIdx.x, b = blockIdx.y, tid = threadIdx.x;
    __shared__ float red[256];
    float pen[6], macc[6];
    const float minv = g_min - 20.0f;
    #pragma unroll
    for (int k = 0; k < 6; k++) {
        int m = tid + k * 256;
        pen[k]  = (maskw[n * NSEQ + m] != 0) ? 0.0f : minv;
        macc[k] = 0.0f;
    }
    for (int h = 0; h < NHEAD; h++) {
        float* row = g_scores + ((size_t)((b * NHEAD + h) * NSEQ + n)) * NSEQ;
        float s[6];
        float lmax = -3.402823466e38f;
        #pragma unroll
        for (int k = 0; k < 6; k++) {
            float v = row[tid + k * 256] + pen[k];
            s[k] = v; macc[k] += v;
            lmax = fmaxf(lmax, v);
        }
        red[tid] = lmax; __syncthreads();
        #pragma unroll
        for (int st = 128; st > 0; st >>= 1) {
            if (tid < st) red[tid] = fmaxf(red[tid], red[tid + st]);
            __syncthreads();
        }
        const float rmax = red[0]; __syncthreads();
        float lsum = 0.0f;
        #pragma unroll
        for (int k = 0; k < 6; k++) { s[k] = __expf(s[k] - rmax); lsum += s[k]; }
        red[tid] = lsum; __syncthreads();
        #pragma unroll
        for (int st = 128; st > 0; st >>= 1) {
            if (tid < st) red[tid] += red[tid + st];
            __syncthreads();
        }
        const float inv = 1.0f / red[0]; __syncthreads();
        #pragma unroll
        for (int k = 0; k < 6; k++) row[tid + k * 256] = s[k] * inv;
    }
    float* om = out_mean + ((size_t)(b * NSEQ + n)) * NSEQ;
    #pragma unroll
    for (int k = 0; k < 6; k++) om[tid + k * 256] = macc[k] * 0.125f;
}

// =======================================================================
// PV (tensor core): x[b, d*8+h, n] = sum_m P[b,h,n,m] v[b, d*8+h, m]
// block tile 128(n) x 64(dim), BK=16, 8 warps (4x2), warp 32x32
// grid (NSEQ/128, 1, B*H), 256 threads. Output staged via smem transpose.
// =======================================================================
__global__ __launch_bounds__(256) void attn_pv_tc() {
    __shared__ __align__(16) char smemraw[64 * 132 * 4];        // 33792 B (>= 13312 A/B)
    uint32_t (*As)[136] = (uint32_t(*)[136])smemraw;             // As[m][n], 16x136
    uint32_t (*Bs)[72]  = (uint32_t(*)[72])(smemraw + 16 * 136 * 4); // Bs[m][dim], 16x72
    float    (*Xs)[132] = (float(*)[132])smemraw;                // Xs[dim][n], 64x132

    const int z = blockIdx.z, b = z >> 3, h = z & 7;
    const int n0 = blockIdx.x * 128;
    const float* sbase = g_scores + (size_t)z * NSEQ * NSEQ;
    const float* vb    = g_v + (size_t)b * DCH * NSEQ + (size_t)h * NSEQ;
    float*       xb    = g_x + (size_t)b * DCH * NSEQ + (size_t)h * NSEQ;
    const int tid = threadIdx.x;
    const int warp = tid >> 5, lane = tid & 31;
    const int g = lane >> 2, tg = lane & 3;
    const int mo = (warp >> 1) * 32;   // n-origin within block
    const int no = (warp & 1) * 32;    // dim-origin within block

    float acc[2][4][4] = {};

    for (int k0 = 0; k0 < NSEQ; k0 += 16) {
        // A: 128 n x 16 m  (probs; coalesced float4 along m, transpose into smem)
        #pragma unroll
        for (int r = 0; r < 2; r++) {
            int i = r * 256 + tid;
            int n = i >> 2, mq = i & 3;
            float4 p4 = *(const float4*)(sbase + (size_t)(n0 + n) * NSEQ + k0 + mq * 4);
            As[mq * 4 + 0][n] = f2tf32(p4.x);
            As[mq * 4 + 1][n] = f2tf32(p4.y);
            As[mq * 4 + 2][n] = f2tf32(p4.z);
            As[mq * 4 + 3][n] = f2tf32(p4.w);
        }
        // B: 64 dim x 16 m (v; coalesced float4 along m, transpose into smem)
        {
            int dim = tid >> 2, mq = tid & 3;
            float4 v4 = *(const float4*)(vb + (size_t)dim * 8 * NSEQ + k0 + mq * 4);
            Bs[mq * 4 + 0][dim] = f2tf32(v4.x);
            Bs[mq * 4 + 1][dim] = f2tf32(v4.y);
            Bs[mq * 4 + 2][dim] = f2tf32(v4.z);
            Bs[mq * 4 + 3][dim] = f2tf32(v4.w);
        }
        __syncthreads();
        #pragma unroll
        for (int kk = 0; kk < 16; kk += 8) {
            uint32_t a[2][4], bb[4][2];
            #pragma unroll
            for (int i = 0; i < 2; i++) {
                a[i][0] = As[kk + tg][mo + i * 16 + g];
                a[i][1] = As[kk + tg][mo + i * 16 + 8 + g];
                a[i][2] = As[kk + tg + 4][mo + i * 16 + g];
                a[i][3] = As[kk + tg + 4][mo + i * 16 + 8 + g];
            }
            #pragma unroll
            for (int j = 0; j < 4; j++) {
                bb[j][0] = Bs[kk + tg][no + j * 8 + g];
                bb[j][1] = Bs[kk + tg + 4][no + j * 8 + g];
            }
            #pragma unroll
            for (int i = 0; i < 2; i++)
                #pragma unroll
                for (int j = 0; j < 4; j++)
                    mma_tf32(acc[i][j], a[i], bb[j]);
        }
        __syncthreads();
    }
    // stage C -> Xs[dim][n] (conflict-free: bank = 8tg+g), then coalesced write
    #pragma unroll
    for (int i = 0; i < 2; i++) {
        int r0 = mo + i * 16 + g;   // n within block
        #pragma unroll
        for (int j = 0; j < 4; j++) {
            int d0 = no + j * 8 + 2 * tg;
            Xs[d0][r0]         = acc[i][j][0];
            Xs[d0 + 1][r0]     = acc[i][j][1];
            Xs[d0][r0 + 8]     = acc[i][j][2];
            Xs[d0 + 1][r0 + 8] = acc[i][j][3];
        }
    }
    __syncthreads();
    #pragma unroll
    for (int r = 0; r < 8; r++) {
        int i = r * 256 + tid;
        int dim = i >> 5, nq = i & 31;
        float4 v = *(float4*)&Xs[dim][nq * 4];
        *(float4*)(xb + (size_t)dim * 8 * NSEQ + n0 + nq * 4) = v;
    }
}

// ---------------- launch ----------------------------------------------------
extern "C" void kernel_launch(void* const* d_in, const int* in_sizes, int n_in,
                              void* d_out, int out_size) {
    const float* query = (const float*)d_in[0];
    const float* key   = (const float*)d_in[1];
    const float* value = (const float*)d_in[2];
    // d_in[3] = dist (unused by the reference)
    const int*   maskw = (const int*)d_in[4];
    const float* Wq = (const float*)d_in[5];
    const float* bq = (const float*)d_in[6];
    const float* Wk = (const float*)d_in[7];
    const float* bk = (const float*)d_in[8];
    const float* Wv = (const float*)d_in[9];
    const float* bv = (const float*)d_in[10];
    const float* Wm = (const float*)d_in[11];
    const float* bm = (const float*)d_in[12];

    float* out      = (float*)d_out;                      // [B, D, N]
    float* out_mean = out + (size_t)BATCH * DCH * NSEQ;   // [B, N, N]

    float *qp, *kp, *vp, *xp;
    cudaGetSymbolAddress((void**)&qp, g_q);
    cudaGetSymbolAddress((void**)&kp, g_k);
    cudaGetSymbolAddress((void**)&vp, g_v);
    cudaGetSymbolAddress((void**)&xp, g_x);

    dim3 grid_proj(NSEQ / 128, DCH / 128, BATCH);
    dim3 grid_sc(NSEQ / 128, NSEQ / 128, BATCH * NHEAD);
    dim3 grid_pv(NSEQ / 128, 1, BATCH * NHEAD);
    dim3 grid_sm(NSEQ, BATCH);

    init_min_kernel<<<1, 1>>>();
    gemm_proj_tc<<<grid_proj, 256>>>(Wq, query, bq, qp);
    gemm_proj_tc<<<grid_proj, 256>>>(Wk, key,   bk, kp);
    gemm_proj_tc<<<grid_proj, 256>>>(Wv, value, bv, vp);
    attn_scores_tc<<<grid_sc, 256>>>();
    softmax_mean_kernel<<<grid_sm, 256>>>(maskw, out_mean);
    attn_pv_tc<<<grid_pv, 256>>>();
    gemm_proj_tc<<<grid_proj, 256>>>(Wm, xp, bm, out);
}

// round 4
// speedup vs baseline: 2.7967x; 1.0426x over previous
#include <cuda_runtime.h>
#include <math.h>
#include <stdint.h>

#define BATCH 4
#define DCH   512
#define NSEQ  1536
#define NHEAD 8
#define HDIM  64

// ---------------- scratch (device globals; no runtime allocation) ----------
__device__ float g_q[BATCH * DCH * NSEQ];
__device__ float g_k[BATCH * DCH * NSEQ];
__device__ float g_v[BATCH * DCH * NSEQ];
__device__ float g_x[BATCH * DCH * NSEQ];
__device__ float g_scores[(size_t)BATCH * NHEAD * NSEQ * NSEQ]; // 302 MB
__device__ float g_min;

// ---------------- helpers ---------------------------------------------------
__device__ __forceinline__ void atomicMinFloat(float* addr, float val) {
    if (val >= 0.0f) atomicMin((int*)addr, __float_as_int(val));
    else             atomicMax((unsigned int*)addr, __float_as_uint(val));
}

__device__ __forceinline__ uint32_t f2tf32(float f) {
    uint32_t u;
    asm("cvt.rna.tf32.f32 %0, %1;" : "=r"(u) : "f"(f));
    return u;
}

// m16n8k8 tf32 MMA, fp32 accumulate.
// A frag (16x8): a0=(g,tg) a1=(g+8,tg) a2=(g,tg+4) a3=(g+8,tg+4); g=lane>>2, tg=lane&3
// B frag (8x8):  b0=(tg,g) b1=(tg+4,g)
// C frag (16x8): c0=(g,2tg) c1=(g,2tg+1) c2=(g+8,2tg) c3=(g+8,2tg+1)
__device__ __forceinline__ void mma_tf32(float* c, const uint32_t* a, const uint32_t* b) {
    asm volatile(
        "mma.sync.aligned.m16n8k8.row.col.f32.tf32.tf32.f32 "
        "{%0,%1,%2,%3}, {%4,%5,%6,%7}, {%8,%9}, {%0,%1,%2,%3};"
        : "+f"(c[0]), "+f"(c[1]), "+f"(c[2]), "+f"(c[3])
        : "r"(a[0]), "r"(a[1]), "r"(a[2]), "r"(a[3]), "r"(b[0]), "r"(b[1]));
}

__global__ void init_min_kernel() { g_min = 3.402823466e38f; }

// =======================================================================
// Shared projection body: Y[o,n] (+bias) = W[o,c] X[c,n], 128x128 tile, BK=32
// 8 warps (2x4), warp tile 64x32.
// =======================================================================
__device__ __forceinline__ void proj_tile(const float* __restrict__ W,
                                          const float* __restrict__ Xb,
                                          const float* __restrict__ bias,
                                          float* __restrict__ Yb,
                                          int o0, int n0) {
    __shared__ uint32_t As[32][136];   // [k][o]
    __shared__ uint32_t Bs[32][136];   // [k][n]
    const int tid = threadIdx.x;
    const int warp = tid >> 5, lane = tid & 31;
    const int g = lane >> 2, tg = lane & 3;
    const int mo = (warp >> 2) * 64;
    const int no = (warp & 3) * 32;

    float acc[4][4][4] = {};

    for (int k0 = 0; k0 < DCH; k0 += 32) {
        #pragma unroll
        for (int r = 0; r < 4; r++) {
            int i = r * 256 + tid;
            int o = i >> 3, kq = i & 7;
            float4 w4 = *(const float4*)(W + (size_t)(o0 + o) * DCH + k0 + kq * 4);
            As[kq * 4 + 0][o] = f2tf32(w4.x);
            As[kq * 4 + 1][o] = f2tf32(w4.y);
            As[kq * 4 + 2][o] = f2tf32(w4.z);
            As[kq * 4 + 3][o] = f2tf32(w4.w);
        }
        #pragma unroll
        for (int r = 0; r < 4; r++) {
            int i = r * 256 + tid;
            int k = i >> 5, nq = i & 31;
            float4 x4 = *(const float4*)(Xb + (size_t)(k0 + k) * NSEQ + n0 + nq * 4);
            *(uint4*)&Bs[k][nq * 4] =
                make_uint4(f2tf32(x4.x), f2tf32(x4.y), f2tf32(x4.z), f2tf32(x4.w));
        }
        __syncthreads();
        #pragma unroll
        for (int kk = 0; kk < 32; kk += 8) {
            uint32_t a[4][4], bb[4][2];
            #pragma unroll
            for (int i = 0; i < 4; i++) {
                a[i][0] = As[kk + tg][mo + i * 16 + g];
                a[i][1] = As[kk + tg][mo + i * 16 + 8 + g];
                a[i][2] = As[kk + tg + 4][mo + i * 16 + g];
                a[i][3] = As[kk + tg + 4][mo + i * 16 + 8 + g];
            }
            #pragma unroll
            for (int j = 0; j < 4; j++) {
                bb[j][0] = Bs[kk + tg][no + j * 8 + g];
                bb[j][1] = Bs[kk + tg + 4][no + j * 8 + g];
            }
            #pragma unroll
            for (int i = 0; i < 4; i++)
                #pragma unroll
                for (int j = 0; j < 4; j++)
                    mma_tf32(acc[i][j], a[i], bb[j]);
        }
        __syncthreads();
    }
    #pragma unroll
    for (int i = 0; i < 4; i++) {
        int r0 = o0 + mo + i * 16 + g;
        int r1 = r0 + 8;
        float bv0 = bias[r0], bv1 = bias[r1];
        #pragma unroll
        for (int j = 0; j < 4; j++) {
            int col = n0 + no + j * 8 + 2 * tg;
            *(float2*)&Yb[(size_t)r0 * NSEQ + col] =
                make_float2(acc[i][j][0] + bv0, acc[i][j][1] + bv0);
            *(float2*)&Yb[(size_t)r1 * NSEQ + col] =
                make_float2(acc[i][j][2] + bv1, acc[i][j][3] + bv1);
        }
    }
}

// q/k/v projections in one launch: grid (12, 4, 12); z = proj*4 + batch
__global__ __launch_bounds__(256) void gemm_proj_qkv(
    const float* __restrict__ query, const float* __restrict__ key,
    const float* __restrict__ value,
    const float* __restrict__ Wq, const float* __restrict__ Wk,
    const float* __restrict__ Wv,
    const float* __restrict__ bq, const float* __restrict__ bk,
    const float* __restrict__ bv) {
    const int z = blockIdx.z, p = z >> 2, b = z & 3;
    const float* W  = (p == 0) ? Wq : (p == 1) ? Wk : Wv;
    const float* X  = ((p == 0) ? query : (p == 1) ? key : value) + (size_t)b * DCH * NSEQ;
    const float* bi = (p == 0) ? bq : (p == 1) ? bk : bv;
    float* Y = ((p == 0) ? g_q : (p == 1) ? g_k : g_v) + (size_t)b * DCH * NSEQ;
    proj_tile(W, X, bi, Y, blockIdx.y * 128, blockIdx.x * 128);
}

__global__ __launch_bounds__(256) void gemm_proj_out(const float* __restrict__ Wm,
                                                     const float* __restrict__ bm,
                                                     float* __restrict__ out) {
    const int b = blockIdx.z;
    proj_tile(Wm, g_x + (size_t)b * DCH * NSEQ, bm, out + (size_t)b * DCH * NSEQ,
              blockIdx.y * 128, blockIdx.x * 128);
}

// =======================================================================
// Scores: S[b,h,n,m] = (1/8) sum_d q k; store raw + global min. BK=32.
// grid (12 m, 12 n, 32 z), 256 threads
// =======================================================================
__global__ __launch_bounds__(256) void attn_scores_tc() {
    __shared__ uint32_t As[32][136];   // [d][n]
    __shared__ uint32_t Bs[32][136];   // [d][m]
    const int z = blockIdx.z, b = z >> 3, h = z & 7;
    const int n0 = blockIdx.y * 128, m0 = blockIdx.x * 128;
    const float* qb = g_q + (size_t)b * DCH * NSEQ + (size_t)h * NSEQ;
    const float* kb = g_k + (size_t)b * DCH * NSEQ + (size_t)h * NSEQ;
    const int tid = threadIdx.x;
    const int warp = tid >> 5, lane = tid & 31;
    const int g = lane >> 2, tg = lane & 3;
    const int mo = (warp >> 2) * 64;
    const int no = (warp & 3) * 32;

    float acc[4][4][4] = {};

    for (int k0 = 0; k0 < HDIM; k0 += 32) {
        #pragma unroll
        for (int r = 0; r < 4; r++) {
            int i = r * 256 + tid;
            int d = i >> 5, nq = i & 31;
            size_t roff = (size_t)(k0 + d) * 8 * NSEQ;
            float4 q4 = *(const float4*)(qb + roff + n0 + nq * 4);
            float4 k4 = *(const float4*)(kb + roff + m0 + nq * 4);
            *(uint4*)&As[d][nq * 4] = make_uint4(f2tf32(q4.x), f2tf32(q4.y), f2tf32(q4.z), f2tf32(q4.w));
            *(uint4*)&Bs[d][nq * 4] = make_uint4(f2tf32(k4.x), f2tf32(k4.y), f2tf32(k4.z), f2tf32(k4.w));
        }
        __syncthreads();
        #pragma unroll
        for (int kk = 0; kk < 32; kk += 8) {
            uint32_t a[4][4], bb[4][2];
            #pragma unroll
            for (int i = 0; i < 4; i++) {
                a[i][0] = As[kk + tg][mo + i * 16 + g];
                a[i][1] = As[kk + tg][mo + i * 16 + 8 + g];
                a[i][2] = As[kk + tg + 4][mo + i * 16 + g];
                a[i][3] = As[kk + tg + 4][mo + i * 16 + 8 + g];
            }
            #pragma unroll
            for (int j = 0; j < 4; j++) {
                bb[j][0] = Bs[kk + tg][no + j * 8 + g];
                bb[j][1] = Bs[kk + tg + 4][no + j * 8 + g];
            }
            #pragma unroll
            for (int i = 0; i < 4; i++)
                #pragma unroll
                for (int j = 0; j < 4; j++)
                    mma_tf32(acc[i][j], a[i], bb[j]);
        }
        __syncthreads();
    }
    float lmin = 3.402823466e38f;
    const size_t sbase = (size_t)z * NSEQ * NSEQ;
    #pragma unroll
    for (int i = 0; i < 4; i++) {
        int r0 = n0 + mo + i * 16 + g;
        int r1 = r0 + 8;
        #pragma unroll
        for (int j = 0; j < 4; j++) {
            int col = m0 + no + j * 8 + 2 * tg;
            float s0 = acc[i][j][0] * 0.125f, s1 = acc[i][j][1] * 0.125f;
            float s2 = acc[i][j][2] * 0.125f, s3 = acc[i][j][3] * 0.125f;
            lmin = fminf(lmin, fminf(fminf(s0, s1), fminf(s2, s3)));
            *(float2*)&g_scores[sbase + (size_t)r0 * NSEQ + col] = make_float2(s0, s1);
            *(float2*)&g_scores[sbase + (size_t)r1 * NSEQ + col] = make_float2(s2, s3);
        }
    }
    #pragma unroll
    for (int o = 16; o > 0; o >>= 1)
        lmin = fminf(lmin, __shfl_xor_sync(0xFFFFFFFFu, lmin, o));
    __shared__ float red[8];
    if (lane == 0) red[warp] = lmin;
    __syncthreads();
    if (warp == 0) {
        float v = (lane < 8) ? red[lane] : 3.402823466e38f;
        #pragma unroll
        for (int o = 4; o > 0; o >>= 1)
            v = fminf(v, __shfl_xor_sync(0xFFFFFFFFu, v, o));
        if (lane == 0) atomicMinFloat(&g_min, v);
    }
}

// =======================================================================
// Head-mean as GEMM: out_mean[b,n,m] = (1/64) sum_{c<512} q[c,n]k[c,m] + pen
// grid (12 m, 12 n, 4 b), 256 threads, BK=32
// =======================================================================
__global__ __launch_bounds__(256) void mean_gemm_tc(const int* __restrict__ maskw,
                                                    float* __restrict__ out_mean) {
    __shared__ uint32_t As[32][136];   // [c][n]
    __shared__ uint32_t Bs[32][136];   // [c][m]
    const int b = blockIdx.z;
    const int n0 = blockIdx.y * 128, m0 = blockIdx.x * 128;
    const float* qb = g_q + (size_t)b * DCH * NSEQ;
    const float* kb = g_k + (size_t)b * DCH * NSEQ;
    const int tid = threadIdx.x;
    const int warp = tid >> 5, lane = tid & 31;
    const int g = lane >> 2, tg = lane & 3;
    const int mo = (warp >> 2) * 64;
    const int no = (warp & 3) * 32;

    float acc[4][4][4] = {};

    for (int k0 = 0; k0 < DCH; k0 += 32) {
        #pragma unroll
        for (int r = 0; r < 4; r++) {
            int i = r * 256 + tid;
            int c = i >> 5, nq = i & 31;
            float4 q4 = *(const float4*)(qb + (size_t)(k0 + c) * NSEQ + n0 + nq * 4);
            float4 k4 = *(const float4*)(kb + (size_t)(k0 + c) * NSEQ + m0 + nq * 4);
            *(uint4*)&As[c][nq * 4] = make_uint4(f2tf32(q4.x), f2tf32(q4.y), f2tf32(q4.z), f2tf32(q4.w));
            *(uint4*)&Bs[c][nq * 4] = make_uint4(f2tf32(k4.x), f2tf32(k4.y), f2tf32(k4.z), f2tf32(k4.w));
        }
        __syncthreads();
        #pragma unroll
        for (int kk = 0; kk < 32; kk += 8) {
            uint32_t a[4][4], bb[4][2];
            #pragma unroll
            for (int i = 0; i < 4; i++) {
                a[i][0] = As[kk + tg][mo + i * 16 + g];
                a[i][1] = As[kk + tg][mo + i * 16 + 8 + g];
                a[i][2] = As[kk + tg + 4][mo + i * 16 + g];
                a[i][3] = As[kk + tg + 4][mo + i * 16 + 8 + g];
            }
            #pragma unroll
            for (int j = 0; j < 4; j++) {
                bb[j][0] = Bs[kk + tg][no + j * 8 + g];
                bb[j][1] = Bs[kk + tg + 4][no + j * 8 + g];
            }
            #pragma unroll
            for (int i = 0; i < 4; i++)
                #pragma unroll
                for (int j = 0; j < 4; j++)
                    mma_tf32(acc[i][j], a[i], bb[j]);
        }
        __syncthreads();
    }
    const float minv = g_min - 20.0f;
    float* om = out_mean + (size_t)b * NSEQ * NSEQ;
    #pragma unroll
    for (int i = 0; i < 4; i++) {
        int r0 = n0 + mo + i * 16 + g;
        int r1 = r0 + 8;
        #pragma unroll
        for (int j = 0; j < 4; j++) {
            int col = m0 + no + j * 8 + 2 * tg;
            int2 mk0 = *(const int2*)(maskw + (size_t)r0 * NSEQ + col);
            int2 mk1 = *(const int2*)(maskw + (size_t)r1 * NSEQ + col);
            *(float2*)&om[(size_t)r0 * NSEQ + col] = make_float2(
                acc[i][j][0] * 0.015625f + (mk0.x ? 0.f : minv),
                acc[i][j][1] * 0.015625f + (mk0.y ? 0.f : minv));
            *(float2*)&om[(size_t)r1 * NSEQ + col] = make_float2(
                acc[i][j][2] * 0.015625f + (mk1.x ? 0.f : minv),
                acc[i][j][3] * 0.015625f + (mk1.y ? 0.f : minv));
        }
    }
}

// =======================================================================
// Fused softmax + PV (max-free): x = (sum_m e_{nm} v_m) / (sum_m e_{nm}),
// e = exp(s + pen). Single pass over scores. BK=32, warp 32n x 32d.
// grid (12, 1, 32), 256 threads
// =======================================================================
__global__ __launch_bounds__(256) void attn_pv_softmax_tc(const int* __restrict__ maskw) {
    __shared__ __align__(16) char smemraw[34816];
    uint32_t (*As)[136] = (uint32_t(*)[136])smemraw;               // exp(s) tf32, [m][n] 32x136
    uint32_t (*Bs)[72]  = (uint32_t(*)[72])(smemraw + 17408);      // v tf32, [m][dim] 32x72
    float    (*Xs)[132] = (float(*)[132])smemraw;                  // out stage [dim][n] 64x132
    float*   rowsum2    = (float*)(smemraw + 33792);               // [2][128]

    const int z = blockIdx.z, b = z >> 3, h = z & 7;
    const int n0 = blockIdx.x * 128;
    const float* sb = g_scores + (size_t)z * NSEQ * NSEQ;
    const float* vb = g_v + (size_t)b * DCH * NSEQ + (size_t)h * NSEQ;
    float*       xb = g_x + (size_t)b * DCH * NSEQ + (size_t)h * NSEQ;
    const int tid = threadIdx.x;
    const int warp = tid >> 5, lane = tid & 31;
    const int g = lane >> 2, tg = lane & 3;
    const int mo = (warp >> 1) * 32;   // n-origin within block
    const int no = (warp & 1) * 32;    // dim-origin within block
    const int myn = tid & 127, half = tid >> 7;
    const float minv = g_min - 20.0f;

    float acc[2][4][4] = {};
    float rsum = 0.0f;

    for (int k0 = 0; k0 < NSEQ; k0 += 32) {
        // scores tile + mask -> exp -> As[m][n]
        #pragma unroll
        for (int r = 0; r < 4; r++) {
            int i = r * 256 + tid;
            int n = i >> 3, mq = i & 7;
            size_t goff = (size_t)(n0 + n) * NSEQ + k0 + mq * 4;
            float4 s4 = *(const float4*)(sb + goff);
            int4   mk = *(const int4*)(maskw + goff);
            float e0 = __expf(s4.x + (mk.x ? 0.f : minv));
            float e1 = __expf(s4.y + (mk.y ? 0.f : minv));
            float e2 = __expf(s4.z + (mk.z ? 0.f : minv));
            float e3 = __expf(s4.w + (mk.w ? 0.f : minv));
            As[mq * 4 + 0][n] = f2tf32(e0);
            As[mq * 4 + 1][n] = f2tf32(e1);
            As[mq * 4 + 2][n] = f2tf32(e2);
            As[mq * 4 + 3][n] = f2tf32(e3);
        }
        // V tile -> Bs[m][dim]
        #pragma unroll
        for (int r = 0; r < 2; r++) {
            int i = r * 256 + tid;
            int dim = i >> 3, mq = i & 7;
            float4 v4 = *(const float4*)(vb + (size_t)dim * 8 * NSEQ + k0 + mq * 4);
            Bs[mq * 4 + 0][dim] = f2tf32(v4.x);
            Bs[mq * 4 + 1][dim] = f2tf32(v4.y);
            Bs[mq * 4 + 2][dim] = f2tf32(v4.z);
            Bs[mq * 4 + 3][dim] = f2tf32(v4.w);
        }
        __syncthreads();
        // row-sum partial (tf32 bits are valid fp32; each (half, n) owned by one thread)
        #pragma unroll
        for (int m = 0; m < 16; m++)
            rsum += __uint_as_float(As[half * 16 + m][myn]);
        // PV mma
        #pragma unroll
        for (int kk = 0; kk < 32; kk += 8) {
            uint32_t a[2][4], bb[4][2];
            #pragma unroll
            for (int i = 0; i < 2; i++) {
                a[i][0] = As[kk + tg][mo + i * 16 + g];
                a[i][1] = As[kk + tg][mo + i * 16 + 8 + g];
                a[i][2] = As[kk + tg + 4][mo + i * 16 + g];
                a[i][3] = As[kk + tg + 4][mo + i * 16 + 8 + g];
            }
            #pragma unroll
            for (int j = 0; j < 4; j++) {
                bb[j][0] = Bs[kk + tg][no + j * 8 + g];
                bb[j][1] = Bs[kk + tg + 4][no + j * 8 + g];
            }
            #pragma unroll
            for (int i = 0; i < 2; i++)
                #pragma unroll
                for (int j = 0; j < 4; j++)
                    mma_tf32(acc[i][j], a[i], bb[j]);
        }
        __syncthreads();
    }
    rowsum2[half * 128 + myn] = rsum;
    __syncthreads();
    // normalize + stage to Xs[dim][n] (Xs aliases As/Bs; all reads done)
    #pragma unroll
    for (int i = 0; i < 2; i++) {
        int r0 = mo + i * 16 + g;
        float inv0 = 1.0f / (rowsum2[r0] + rowsum2[128 + r0]);
        float inv8 = 1.0f / (rowsum2[r0 + 8] + rowsum2[128 + r0 + 8]);
        #pragma unroll
        for (int j = 0; j < 4; j++) {
            int d0 = no + j * 8 + 2 * tg;
            Xs[d0][r0]         = acc[i][j][0] * inv0;
            Xs[d0 + 1][r0]     = acc[i][j][1] * inv0;
            Xs[d0][r0 + 8]     = acc[i][j][2] * inv8;
            Xs[d0 + 1][r0 + 8] = acc[i][j][3] * inv8;
        }
    }
    __syncthreads();
    #pragma unroll
    for (int r = 0; r < 8; r++) {
        int i = r * 256 + tid;
        int dim = i >> 5, nq = i & 31;
        *(float4*)(xb + (size_t)dim * 8 * NSEQ + n0 + nq * 4) = *(float4*)&Xs[dim][nq * 4];
    }
}

// ---------------- launch ----------------------------------------------------
extern "C" void kernel_launch(void* const* d_in, const int* in_sizes, int n_in,
                              void* d_out, int out_size) {
    const float* query = (const float*)d_in[0];
    const float* key   = (const float*)d_in[1];
    const float* value = (const float*)d_in[2];
    // d_in[3] = dist (unused by the reference)
    const int*   maskw = (const int*)d_in[4];
    const float* Wq = (const float*)d_in[5];
    const float* bq = (const float*)d_in[6];
    const float* Wk = (const float*)d_in[7];
    const float* bk = (const float*)d_in[8];
    const float* Wv = (const float*)d_in[9];
    const float* bv = (const float*)d_in[10];
    const float* Wm = (const float*)d_in[11];
    const float* bm = (const float*)d_in[12];

    float* out      = (float*)d_out;                      // [B, D, N]
    float* out_mean = out + (size_t)BATCH * DCH * NSEQ;   // [B, N, N]

    dim3 grid_qkv(NSEQ / 128, DCH / 128, BATCH * 3);
    dim3 grid_proj(NSEQ / 128, DCH / 128, BATCH);
    dim3 grid_sc(NSEQ / 128, NSEQ / 128, BATCH * NHEAD);
    dim3 grid_mean(NSEQ / 128, NSEQ / 128, BATCH);
    dim3 grid_pv(NSEQ / 128, 1, BATCH * NHEAD);

    init_min_kernel<<<1, 1>>>();
    gemm_proj_qkv<<<grid_qkv, 256>>>(query, key, value, Wq, Wk, Wv, bq, bk, bv);
    attn_scores_tc<<<grid_sc, 256>>>();
    mean_gemm_tc<<<grid_mean, 256>>>(maskw, out_mean);
    attn_pv_softmax_tc<<<grid_pv, 256>>>(maskw);
    gemm_proj_out<<<grid_proj, 256>>>(Wm, bm, out);
}